// round 1
// baseline (speedup 1.0000x reference)
#include <cuda_runtime.h>

typedef unsigned long long u64;

#define Bsz   4096
#define Tt    512
#define HID   32
#define FOUT  20
#define WARPS 8
#define PAIRS 2                    // f32x2 pairs per warp -> 4 samples/warp
#define SPW   (PAIRS * 2)          // samples per warp
#define SPB   (WARPS * SPW)        // 32 samples per block
#define NBLK  (Bsz / SPB)          // 128 blocks

// ---- shared memory layout (in floats) ----
#define OW1  0                      // [34][32][4]  L1 weights, gate-packed float4
#define OW2  (OW1 + 34*32*4)        // [64][32][4]  L2 weights (ih2|hh2 concat)
#define OWO  (OW2 + 64*32*4)        // [32][20]     W_out transposed
#define OB1  (OWO + 32*20)          // [32][4]      b1 gate-packed
#define OB2  (OB1 + 32*4)           // [32][4]
#define OBO  (OB2 + 32*4)           // [20]
#define OZ1  (OBO + 20)             // [WARPS*PAIRS][34][2]  (x0,x1,h1_prev) pairs
#define OZ2  (OZ1 + WARPS*PAIRS*34*2) // [WARPS*PAIRS][64][2]  (h1_cur | h2_prev) pairs
#define SMEM_FLOATS (OZ2 + WARPS*PAIRS*64*2)
#define SMEM_BYTES  (SMEM_FLOATS * 4)

__device__ __forceinline__ u64 pk(float lo, float hi) {
    u64 r; asm("mov.b64 %0, {%1, %2};" : "=l"(r) : "f"(lo), "f"(hi)); return r;
}
__device__ __forceinline__ void upk(u64 v, float& lo, float& hi) {
    asm("mov.b64 {%0, %1}, %2;" : "=f"(lo), "=f"(hi) : "l"(v));
}
__device__ __forceinline__ u64 fma2(u64 a, u64 b, u64 c) {
    u64 d; asm("fma.rn.f32x2 %0, %1, %2, %3;" : "=l"(d) : "l"(a), "l"(b), "l"(c)); return d;
}
__device__ __forceinline__ u64 mul2(u64 a, u64 b) {
    u64 d; asm("mul.rn.f32x2 %0, %1, %2;" : "=l"(d) : "l"(a), "l"(b)); return d;
}
__device__ __forceinline__ float sigmf(float x) {
    return __fdividef(1.f, 1.f + __expf(-x));
}
__device__ __forceinline__ float tanhfast(float x) {
    float a = fabsf(x);
    float e = __expf(-2.f * a);
    float t = __fdividef(1.f - e, 1.f + e);
    return copysignf(t, x);
}

// LSTM gate epilogue for one f32x2 pair: gates (i,f,g,o) pre-activations -> new h pair; c updated in place.
__device__ __forceinline__ u64 lstm_epi(u64 ai, u64 af, u64 ag, u64 ao, u64& c) {
    float i0, i1, f0, f1, g0, g1, o0, o1;
    upk(ai, i0, i1); upk(af, f0, f1); upk(ag, g0, g1); upk(ao, o0, o1);
    i0 = sigmf(i0); i1 = sigmf(i1);
    f0 = sigmf(f0); f1 = sigmf(f1);
    g0 = tanhfast(g0); g1 = tanhfast(g1);
    o0 = sigmf(o0); o1 = sigmf(o1);
    u64 ig = mul2(pk(i0, i1), pk(g0, g1));
    c = fma2(pk(f0, f1), c, ig);
    float ca, cb; upk(c, ca, cb);
    return pk(o0 * tanhfast(ca), o1 * tanhfast(cb));
}

__global__ void __launch_bounds__(WARPS * 32, 1)
lstm_seq_kernel(const float* __restrict__ x,
                const float* __restrict__ Wih1, const float* __restrict__ Whh1,
                const float* __restrict__ bih1, const float* __restrict__ bhh1,
                const float* __restrict__ Wih2, const float* __restrict__ Whh2,
                const float* __restrict__ bih2, const float* __restrict__ bhh2,
                const float* __restrict__ Wout, const float* __restrict__ bout,
                float* __restrict__ out)
{
    extern __shared__ float sm[];
    const int tid = threadIdx.x;

    // ---- stage weights into shared (transposed, gate-packed) ----
    // L1: input z1 = [x0, x1, h1(32)]  (34 rows). sm[OW1 + (k*32 + j)*4 + g] = W1[g*32+j][k]
    for (int idx = tid; idx < 34 * 32; idx += blockDim.x) {
        int k = idx >> 5, j = idx & 31;
        #pragma unroll
        for (int g = 0; g < 4; g++) {
            float v = (k < 2) ? Wih1[(g * 32 + j) * 2 + k]
                              : Whh1[(g * 32 + j) * 32 + (k - 2)];
            sm[OW1 + idx * 4 + g] = v;
        }
    }
    // L2: input z2 = [h1(32), h2(32)]  (64 rows)
    for (int idx = tid; idx < 64 * 32; idx += blockDim.x) {
        int k = idx >> 5, j = idx & 31;
        #pragma unroll
        for (int g = 0; g < 4; g++) {
            float v = (k < 32) ? Wih2[(g * 32 + j) * 32 + k]
                               : Whh2[(g * 32 + j) * 32 + (k - 32)];
            sm[OW2 + idx * 4 + g] = v;
        }
    }
    // W_out transposed: sm[OWO + k*20 + o] = Wout[o][k]
    for (int idx = tid; idx < 32 * 20; idx += blockDim.x) {
        int k = idx / 20, o = idx % 20;
        sm[OWO + idx] = Wout[o * 32 + k];
    }
    // biases (combined), gate-packed
    for (int idx = tid; idx < 32; idx += blockDim.x) {
        #pragma unroll
        for (int g = 0; g < 4; g++) {
            sm[OB1 + idx * 4 + g] = bih1[g * 32 + idx] + bhh1[g * 32 + idx];
            sm[OB2 + idx * 4 + g] = bih2[g * 32 + idx] + bhh2[g * 32 + idx];
        }
    }
    for (int idx = tid; idx < FOUT; idx += blockDim.x) sm[OBO + idx] = bout[idx];
    // zero state exchange buffers (h, c initial state = 0)
    for (int idx = tid; idx < WARPS * PAIRS * 34 * 2; idx += blockDim.x) sm[OZ1 + idx] = 0.f;
    for (int idx = tid; idx < WARPS * PAIRS * 64 * 2; idx += blockDim.x) sm[OZ2 + idx] = 0.f;
    __syncthreads();

    const int w    = tid >> 5;
    const int lane = tid & 31;
    const int sWarp = blockIdx.x * SPB + w * SPW;   // first sample of this warp

    float* z1 = sm + OZ1 + (w * PAIRS) * 34 * 2;    // pair p at +p*68
    float* z2 = sm + OZ2 + (w * PAIRS) * 64 * 2;    // pair p at +p*128

    u64 c1[PAIRS], c2[PAIRS];
    #pragma unroll
    for (int p = 0; p < PAIRS; p++) { c1[p] = 0ull; c2[p] = 0ull; }

    // prefetch x(t=0): lanes 0..SPW-1 each own one sample
    float2 xv = make_float2(0.f, 0.f);
    if (lane < SPW) xv = ((const float2*)x)[(size_t)(sWarp + lane) * Tt];

    const float4 bv1 = *(const float4*)&sm[OB1 + lane * 4];
    const float4 bv2 = *(const float4*)&sm[OB2 + lane * 4];
    const float  bo  = (lane < FOUT) ? sm[OBO + lane] : 0.f;

    for (int t = 0; t < Tt; t++) {
        // ---- store x_t into z1 slots 0..1 ----
        if (lane < SPW) {
            int p = lane >> 1, half = lane & 1;
            z1[(p * 34 + 0) * 2 + half] = xv.x;
            z1[(p * 34 + 1) * 2 + half] = xv.y;
        }
        __syncwarp();
        if (lane < SPW && t + 1 < Tt)
            xv = ((const float2*)x)[(size_t)(sWarp + lane) * Tt + t + 1];

        // ---- layer 1 accumulate: gates[g][pair] over k=0..33 ----
        u64 a0[PAIRS], a1[PAIRS], a2[PAIRS], a3[PAIRS];
        #pragma unroll
        for (int p = 0; p < PAIRS; p++) {
            a0[p] = pk(bv1.x, bv1.x); a1[p] = pk(bv1.y, bv1.y);
            a2[p] = pk(bv1.z, bv1.z); a3[p] = pk(bv1.w, bv1.w);
        }
        #pragma unroll
        for (int k = 0; k < 34; k++) {
            float4 wv = *(const float4*)&sm[OW1 + (k * 32 + lane) * 4];
            u64 w0 = pk(wv.x, wv.x), w1 = pk(wv.y, wv.y);
            u64 w2 = pk(wv.z, wv.z), w3 = pk(wv.w, wv.w);
            #pragma unroll
            for (int p = 0; p < PAIRS; p++) {
                u64 zp = *(const u64*)&z1[(p * 34 + k) * 2];
                a0[p] = fma2(w0, zp, a0[p]);
                a1[p] = fma2(w1, zp, a1[p]);
                a2[p] = fma2(w2, zp, a2[p]);
                a3[p] = fma2(w3, zp, a3[p]);
            }
        }
        __syncwarp();   // all lanes done reading z1 before h1 writes

        // ---- layer 1 epilogue: new h1 -> z1[2+lane] (next t) and z2[lane] (layer 2 input) ----
        #pragma unroll
        for (int p = 0; p < PAIRS; p++) {
            u64 hp = lstm_epi(a0[p], a1[p], a2[p], a3[p], c1[p]);
            *(u64*)&z1[(p * 34 + 2 + lane) * 2] = hp;
            *(u64*)&z2[(p * 64 + lane) * 2]     = hp;
        }
        __syncwarp();   // h1 visible

        // ---- layer 2 accumulate over k=0..63 (h1 | h2_prev) ----
        #pragma unroll
        for (int p = 0; p < PAIRS; p++) {
            a0[p] = pk(bv2.x, bv2.x); a1[p] = pk(bv2.y, bv2.y);
            a2[p] = pk(bv2.z, bv2.z); a3[p] = pk(bv2.w, bv2.w);
        }
        #pragma unroll
        for (int k = 0; k < 64; k++) {
            float4 wv = *(const float4*)&sm[OW2 + (k * 32 + lane) * 4];
            u64 w0 = pk(wv.x, wv.x), w1 = pk(wv.y, wv.y);
            u64 w2 = pk(wv.z, wv.z), w3 = pk(wv.w, wv.w);
            #pragma unroll
            for (int p = 0; p < PAIRS; p++) {
                u64 zp = *(const u64*)&z2[(p * 64 + k) * 2];
                a0[p] = fma2(w0, zp, a0[p]);
                a1[p] = fma2(w1, zp, a1[p]);
                a2[p] = fma2(w2, zp, a2[p]);
                a3[p] = fma2(w3, zp, a3[p]);
            }
        }
        __syncwarp();   // all lanes done reading z2 before h2 writes

        // ---- layer 2 epilogue: new h2 -> z2[32+lane] ----
        #pragma unroll
        for (int p = 0; p < PAIRS; p++) {
            u64 hp = lstm_epi(a0[p], a1[p], a2[p], a3[p], c2[p]);
            *(u64*)&z2[(p * 64 + 32 + lane) * 2] = hp;
        }
        __syncwarp();   // h2 visible

        // ---- output head: lanes 0..19 compute out[o] = h2 . Wout[o] + b ----
        if (lane < FOUT) {
            u64 acc[PAIRS];
            #pragma unroll
            for (int p = 0; p < PAIRS; p++) acc[p] = pk(bo, bo);
            #pragma unroll
            for (int k = 0; k < 32; k++) {
                float wo = sm[OWO + k * FOUT + lane];
                u64 wd = pk(wo, wo);
                #pragma unroll
                for (int p = 0; p < PAIRS; p++) {
                    u64 zp = *(const u64*)&z2[(p * 64 + 32 + k) * 2];
                    acc[p] = fma2(wd, zp, acc[p]);
                }
            }
            #pragma unroll
            for (int p = 0; p < PAIRS; p++) {
                float oa, ob; upk(acc[p], oa, ob);
                int sa = sWarp + 2 * p;
                out[((size_t)sa * Tt + t) * FOUT + lane]       = oa;
                out[((size_t)(sa + 1) * Tt + t) * FOUT + lane] = ob;
            }
        }
        // next iteration's syncwarps cover the z2 read/write hazard across steps
    }
}

extern "C" void kernel_launch(void* const* d_in, const int* in_sizes, int n_in,
                              void* d_out, int out_size) {
    const float* x    = (const float*)d_in[0];
    const float* Wih1 = (const float*)d_in[1];
    const float* Whh1 = (const float*)d_in[2];
    const float* bih1 = (const float*)d_in[3];
    const float* bhh1 = (const float*)d_in[4];
    const float* Wih2 = (const float*)d_in[5];
    const float* Whh2 = (const float*)d_in[6];
    const float* bih2 = (const float*)d_in[7];
    const float* bhh2 = (const float*)d_in[8];
    const float* Wout = (const float*)d_in[9];
    const float* bout = (const float*)d_in[10];
    float* out = (float*)d_out;

    cudaFuncSetAttribute(lstm_seq_kernel,
                         cudaFuncAttributeMaxDynamicSharedMemorySize, SMEM_BYTES);
    lstm_seq_kernel<<<NBLK, WARPS * 32, SMEM_BYTES>>>(
        x, Wih1, Whh1, bih1, bhh1, Wih2, Whh2, bih2, bhh2, Wout, bout, out);
}